// round 14
// baseline (speedup 1.0000x reference)
#include <cuda_runtime.h>
#include <cuda_fp16.h>
#include <cstdint>

#define NN      100000
#define NE      600000
#define HID     128
#define NSB     391              // scan blocks: ceil(NN/256)

// ---------------- scratch (device globals; no allocation allowed) ----------
// g_ux[node]: 32 chunks of 16B; chunk c = { u[4c..4c+3], x[4c..4c+3] } in fp16.
__device__ __half g_ux[(size_t)NN * 256];
__device__ float  g_v[(size_t)NN * 128];            // v = x @ W1b, fp32
__device__ __half g_xh[(size_t)NN * 128];           // fp16(x)
__device__ __half g_Bhi[256 * 128];                 // fp16 hi of B[n][k]
__device__ __half g_Blo[256 * 128];                 // fp16 lo of B[n][k]
__device__ int  g_cnt[NN];                          // zeroed by PREVIOUS call's k_edge2
__device__ int  g_off[NN + 1];
__device__ int  g_ptr[NN];
__device__ int  g_bsum[NSB];                        // raw per-block totals
__device__ int2 g_srcw[NE];                         // (src, bits(w)) grouped by tgt

__device__ __forceinline__ uint32_t smem_u32(const void* p) {
    uint32_t a;
    asm("{ .reg .u64 t; cvta.to.shared.u64 t, %1; cvt.u32.u64 %0, t; }"
        : "=r"(a) : "l"(p));
    return a;
}

// ---------------------------------------------------------------------------
// K0: fp16 conversion of x + W hi/lo + FUSED histogram (g_cnt pre-zeroed by
//     the previous call's k_edge2; module init covers the first call).
// ---------------------------------------------------------------------------
__global__ void k_cvt(const float* __restrict__ x, const float* __restrict__ W1,
                      const int* __restrict__ ei) {
    long i = (long)blockIdx.x * blockDim.x + threadIdx.x;
    long stride = (long)gridDim.x * blockDim.x;

    const long n4 = (long)NN * 32;
    const float4* x4 = (const float4*)x;
    for (long j = i; j < n4; j += stride) {
        float4 v = x4[j];
        __half2 xh01 = __floats2half2_rn(v.x, v.y);
        __half2 xh23 = __floats2half2_rn(v.z, v.w);
        uint2 pk = make_uint2(*(uint32_t*)&xh01, *(uint32_t*)&xh23);
        ((uint2*)g_xh)[j] = pk;
        long node = j >> 5, c = j & 31;
        *(uint2*)((char*)g_ux + (size_t)node * 512 + c * 16 + 8) = pk;
    }
    for (long e = i; e < NE; e += stride)
        atomicAdd(&g_cnt[ei[NE + e]], 1);
    for (long j = i; j < 256 * 128; j += stride) {
        int n = (int)(j >> 7), k = (int)(j & 127);
        int q = n >> 7, col = n & 127;
        float wv = W1[(size_t)(q * 128 + k) * 128 + col];
        __half h = __float2half_rn(wv);
        g_Bhi[j] = h;
        g_Blo[j] = __float2half_rn(wv - __half2float(h));
    }
}

// ---------------------------------------------------------------------------
// CSR build: block scan -> (prefix+finalize) -> scatter
// ---------------------------------------------------------------------------
__global__ void k_scan1() {
    const int b = blockIdx.x, t = threadIdx.x;
    const int i = b * 256 + t;
    int v = (i < NN) ? g_cnt[i] : 0;
    const int lane = t & 31, w = t >> 5;
    #pragma unroll
    for (int o = 1; o < 32; o <<= 1) {
        int n = __shfl_up_sync(0xffffffffu, v, o);
        if (lane >= o) v += n;
    }
    __shared__ int ws[8];
    if (lane == 31) ws[w] = v;
    __syncthreads();
    if (w == 0 && lane < 8) {
        int s = ws[lane];
        #pragma unroll
        for (int o = 1; o < 8; o <<= 1) {
            int n = __shfl_up_sync(0xffu, s, o);
            if (lane >= o) s += n;
        }
        ws[lane] = s;
    }
    __syncthreads();
    if (w > 0) v += ws[w - 1];
    if (i < NN) g_off[i + 1] = v;     // block-local inclusive
    if (t == 255) g_bsum[b] = v;      // raw block total
}

__global__ void k_scan23() {
    const int b = blockIdx.x, t = threadIdx.x;
    int part = 0;
    for (int j = t; j < b; j += 256) part += g_bsum[j];
    const int lane = t & 31, w = t >> 5;
    #pragma unroll
    for (int o = 16; o; o >>= 1) part += __shfl_xor_sync(0xffffffffu, part, o);
    __shared__ int ws[8];
    if (lane == 0) ws[w] = part;
    __syncthreads();
    __shared__ int pfx;
    if (t == 0) pfx = ws[0] + ws[1] + ws[2] + ws[3] + ws[4] + ws[5] + ws[6] + ws[7];
    __syncthreads();
    const int prefix = pfx;

    const int j = b * 256 + t;
    if (j == 0) g_off[0] = 0;
    if (j < NN) {
        int incl = g_off[j + 1] + prefix;
        g_off[j + 1] = incl;
        g_ptr[j] = incl - g_cnt[j];
    }
}

__global__ void k_scat(const int* __restrict__ ei, const float* __restrict__ ew) {
    long i = (long)blockIdx.x * blockDim.x + threadIdx.x;
    long stride = (long)gridDim.x * blockDim.x;
    for (long e = i; e < NE; e += stride) {
        int tg = ei[NE + e];
        int pos = atomicAdd(&g_ptr[tg], 1);
        g_srcw[pos] = make_int2(ei[e], __float_as_int(ew[e]));
    }
}

// ---------------------------------------------------------------------------
// K1: tensor-core GEMM (mma.sync fp16, 2-term split), 512 threads/CTA,
//     warp grid 4(m) x 4(n), warp tile 32x32 -> 32 warps/SM at 2 CTA/SM.
// ---------------------------------------------------------------------------
#define ROWB      272
#define AS_OFF    0
#define BH_OFF    (128 * ROWB)
#define BL_OFF    (2 * 128 * ROWB)
#define SMEM_MMA  (3 * 128 * ROWB)

__device__ __forceinline__ void mma_fp16(float* d, const uint32_t* a, const uint32_t* b) {
    asm volatile(
        "mma.sync.aligned.m16n8k16.row.col.f32.f16.f16.f32 "
        "{%0,%1,%2,%3}, {%4,%5,%6,%7}, {%8,%9}, {%0,%1,%2,%3};"
        : "+f"(d[0]), "+f"(d[1]), "+f"(d[2]), "+f"(d[3])
        : "r"(a[0]), "r"(a[1]), "r"(a[2]), "r"(a[3]), "r"(b[0]), "r"(b[1]));
}

__device__ __forceinline__ void ldsm_x4(uint32_t* r, uint32_t addr) {
    asm volatile("ldmatrix.sync.aligned.m8n8.x4.shared.b16 {%0,%1,%2,%3}, [%4];"
                 : "=r"(r[0]), "=r"(r[1]), "=r"(r[2]), "=r"(r[3]) : "r"(addr));
}

__global__ __launch_bounds__(512, 2) void k_mma() {
    extern __shared__ char smem[];
    const uint32_t sbase = smem_u32(smem);
    const int t = threadIdx.x;
    const int q = blockIdx.y;
    const int m0 = blockIdx.x * 128;

    // B panels (hi, lo) for this q: 2048 16B chunks each, 512 threads
    #pragma unroll
    for (int r = 0; r < 4; r++) {
        int idx = t + r * 512;
        int row = idx >> 4, c = idx & 15;
        *(uint4*)(smem + BH_OFF + row * ROWB + c * 16) =
            *(const uint4*)(g_Bhi + (size_t)(q * 128 + row) * 128 + c * 8);
        *(uint4*)(smem + BL_OFF + row * ROWB + c * 16) =
            *(const uint4*)(g_Blo + (size_t)(q * 128 + row) * 128 + c * 8);
    }
    // A panel (single load): 2048 chunks
    #pragma unroll
    for (int r = 0; r < 4; r++) {
        int idx = t + r * 512;
        int row = idx >> 4, c = idx & 15;
        uint4 v = make_uint4(0, 0, 0, 0);
        if (m0 + row < NN)
            v = *(const uint4*)(g_xh + (size_t)(m0 + row) * 128 + c * 8);
        *(uint4*)(smem + AS_OFF + row * ROWB + c * 16) = v;
    }
    __syncthreads();

    const int wid = t >> 5, lane = t & 31;
    const int wm = (wid >> 2) * 32;      // 0/32/64/96
    const int wn = (wid & 3) * 32;       // 0/32/64/96
    const int g  = lane >> 2, tt = lane & 3;

    const uint32_t a_off = (uint32_t)((wm + (lane & 15)) * ROWB + ((lane >> 4) << 4));
    const uint32_t b_off = (uint32_t)((wn + ((lane >> 4) << 3) + (lane & 7)) * ROWB
                                      + (((lane >> 3) & 1) << 4));

    float acc[2][4][4];
    #pragma unroll
    for (int mt = 0; mt < 2; mt++)
        #pragma unroll
        for (int nt = 0; nt < 4; nt++)
            #pragma unroll
            for (int e = 0; e < 4; e++) acc[mt][nt][e] = 0.0f;

    #pragma unroll 1
    for (int term = 0; term < 2; term++) {
        const uint32_t boff = term ? BL_OFF : BH_OFF;
        const uint32_t aB = sbase + AS_OFF + a_off;
        const uint32_t bB = sbase + boff + b_off;
        #pragma unroll 1
        for (int ks = 0; ks < 8; ks++) {
            const uint32_t kb = ks * 32;            // k0*2 bytes
            uint32_t a[2][4], b[2][4];
            ldsm_x4(a[0], aB + kb);
            ldsm_x4(a[1], aB + 16 * ROWB + kb);
            ldsm_x4(b[0], bB + kb);
            ldsm_x4(b[1], bB + 16 * ROWB + kb);
            #pragma unroll
            for (int mt = 0; mt < 2; mt++)
                #pragma unroll
                for (int nt = 0; nt < 4; nt++)
                    mma_fp16(acc[mt][nt], a[mt], &b[nt >> 1][(nt & 1) * 2]);
        }
    }

    #pragma unroll
    for (int mt = 0; mt < 2; mt++) {
        const int r0 = m0 + wm + mt * 16 + g;
        #pragma unroll
        for (int nt = 0; nt < 4; nt++) {
            const int ncol = wn + nt * 8 + tt * 2;
            if (q == 0) {
                const size_t off = (size_t)(ncol >> 2) * 16 + (size_t)(ncol & 3) * 2;
                if (r0 < NN) {
                    __half2 h = __floats2half2_rn(acc[mt][nt][0], acc[mt][nt][1]);
                    *(__half2*)((char*)g_ux + (size_t)r0 * 512 + off) = h;
                }
                if (r0 + 8 < NN) {
                    __half2 h = __floats2half2_rn(acc[mt][nt][2], acc[mt][nt][3]);
                    *(__half2*)((char*)g_ux + (size_t)(r0 + 8) * 512 + off) = h;
                }
            } else {
                if (r0 < NN)
                    *(float2*)(g_v + (size_t)r0 * 128 + ncol) =
                        make_float2(acc[mt][nt][0], acc[mt][nt][1]);
                if (r0 + 8 < NN)
                    *(float2*)(g_v + (size_t)(r0 + 8) * 128 + ncol) =
                        make_float2(acc[mt][nt][2], acc[mt][nt][3]);
            }
        }
    }
}

// ---------------------------------------------------------------------------
// K2: per-TARGET warp; 2-edge loop (proven best); __expf; fp32 accum.
//     ALSO re-zeros g_cnt for the NEXT call (graph replays).
// ---------------------------------------------------------------------------
__global__ __launch_bounds__(256) void k_edge2(
    const float* __restrict__ x,
    const float* __restrict__ W1, const float* __restrict__ b1,
    const float* __restrict__ W2, const float* __restrict__ b2,
    float* __restrict__ out)
{
    __shared__ float sW1c[HID], sb1[HID], sW2[HID];
    __shared__ float sb2;
    const int t = threadIdx.x;
    if (t < HID) {
        sW1c[t] = W1[256 * HID + t];
        sb1[t]  = b1[t];
        sW2[t]  = W2[t];
    }
    if (t == 0) sb2 = b2[0];

    // zero g_cnt for the next call (12500 blocks x 256 thr covers 100k)
    {
        int gi = blockIdx.x * 256 + t;
        if (gi < NN) g_cnt[gi] = 0;
    }
    __syncthreads();

    const int warp = t >> 5, lane = t & 31;
    const int node = blockIdx.x * 8 + warp;

    const int beg = g_off[node], end = g_off[node + 1];

    const float4 v  = ((const float4*)(g_v + (size_t)node * 128))[lane];
    const float4 xt = ((const float4*)(x + (size_t)node * HID))[lane];
    const float4 wc = *(const float4*)&sW1c[lane * 4];
    const float4 bb = *(const float4*)&sb1[lane * 4];
    const float4 w2 = *(const float4*)&sW2[lane * 4];
    const float  lb2 = sb2;

    float sum = 0.0f;
    float4 num = make_float4(0.f, 0.f, 0.f, 0.f);

    int i = beg;
    for (; i + 2 <= end; i += 2) {
        const int2 sw0 = g_srcw[i];
        const int2 sw1 = g_srcw[i + 1];
        const float w0 = __int_as_float(sw0.y);
        const float w1 = __int_as_float(sw1.y);
        const uint4 r0 = *(const uint4*)((const char*)g_ux + (size_t)sw0.x * 512 + lane * 16);
        const uint4 r1 = *(const uint4*)((const char*)g_ux + (size_t)sw1.x * 512 + lane * 16);

        float2 u0a = __half22float2(*(const __half2*)&r0.x);
        float2 u0b = __half22float2(*(const __half2*)&r0.y);
        float2 x0a = __half22float2(*(const __half2*)&r0.z);
        float2 x0b = __half22float2(*(const __half2*)&r0.w);
        float2 u1a = __half22float2(*(const __half2*)&r1.x);
        float2 u1b = __half22float2(*(const __half2*)&r1.y);
        float2 x1a = __half22float2(*(const __half2*)&r1.z);
        float2 x1b = __half22float2(*(const __half2*)&r1.w);

        float a0 = fmaxf(fmaf(w0, wc.x, u0a.x + v.x) + bb.x, 0.f);
        float a1 = fmaxf(fmaf(w0, wc.y, u0a.y + v.y) + bb.y, 0.f);
        float a2 = fmaxf(fmaf(w0, wc.z, u0b.x + v.z) + bb.z, 0.f);
        float a3 = fmaxf(fmaf(w0, wc.w, u0b.y + v.w) + bb.w, 0.f);
        float p0 = a0 * w2.x + a1 * w2.y + a2 * w2.z + a3 * w2.w;

        float c0 = fmaxf(fmaf(w1, wc.x, u1a.x + v.x) + bb.x, 0.f);
        float c1 = fmaxf(fmaf(w1, wc.y, u1a.y + v.y) + bb.y, 0.f);
        float c2 = fmaxf(fmaf(w1, wc.z, u1b.x + v.z) + bb.z, 0.f);
        float c3 = fmaxf(fmaf(w1, wc.w, u1b.y + v.w) + bb.w, 0.f);
        float p1 = c0 * w2.x + c1 * w2.y + c2 * w2.z + c3 * w2.w;

        #pragma unroll
        for (int o = 16; o; o >>= 1) {
            p0 += __shfl_xor_sync(0xffffffffu, p0, o);
            p1 += __shfl_xor_sync(0xffffffffu, p1, o);
        }
        const float e0 = __expf(p0 + lb2);
        const float e1 = __expf(p1 + lb2);
        sum += e0 + e1;
        num.x += e0 * x0a.x + e1 * x1a.x;
        num.y += e0 * x0a.y + e1 * x1a.y;
        num.z += e0 * x0b.x + e1 * x1b.x;
        num.w += e0 * x0b.y + e1 * x1b.y;
    }
    if (i < end) {
        const int2 sw0 = g_srcw[i];
        const float w0 = __int_as_float(sw0.y);
        const uint4 r0 = *(const uint4*)((const char*)g_ux + (size_t)sw0.x * 512 + lane * 16);
        float2 u0a = __half22float2(*(const __half2*)&r0.x);
        float2 u0b = __half22float2(*(const __half2*)&r0.y);
        float2 x0a = __half22float2(*(const __half2*)&r0.z);
        float2 x0b = __half22float2(*(const __half2*)&r0.w);
        float a0 = fmaxf(fmaf(w0, wc.x, u0a.x + v.x) + bb.x, 0.f);
        float a1 = fmaxf(fmaf(w0, wc.y, u0a.y + v.y) + bb.y, 0.f);
        float a2 = fmaxf(fmaf(w0, wc.z, u0b.x + v.z) + bb.z, 0.f);
        float a3 = fmaxf(fmaf(w0, wc.w, u0b.y + v.w) + bb.w, 0.f);
        float p0 = a0 * w2.x + a1 * w2.y + a2 * w2.z + a3 * w2.w;
        #pragma unroll
        for (int o = 16; o; o >>= 1) p0 += __shfl_xor_sync(0xffffffffu, p0, o);
        const float e0 = __expf(p0 + lb2);
        sum += e0;
        num.x += e0 * x0a.x; num.y += e0 * x0a.y;
        num.z += e0 * x0b.x; num.w += e0 * x0b.y;
    }

    const float inv = 1.0f / fmaxf(sum, 1e-12f);
    float4 o4 = make_float4(fmaf(num.x, inv, xt.x), fmaf(num.y, inv, xt.y),
                            fmaf(num.z, inv, xt.z), fmaf(num.w, inv, xt.w));
    ((float4*)(out + (size_t)node * HID))[lane] = o4;
}

// ---------------------------------------------------------------------------
extern "C" void kernel_launch(void* const* d_in, const int* in_sizes, int n_in,
                              void* d_out, int out_size)
{
    const float* x  = (const float*)d_in[0];
    const int*   ei = (const int*)d_in[1];
    const float* ew = (const float*)d_in[2];
    const float* W1 = (const float*)d_in[3];
    const float* b1 = (const float*)d_in[4];
    const float* W2 = (const float*)d_in[5];
    const float* b2 = (const float*)d_in[6];
    float* out = (float*)d_out;

    cudaFuncSetAttribute(k_mma, cudaFuncAttributeMaxDynamicSharedMemorySize, SMEM_MMA);

    // Order keeps the ncu capture window (4th launch) on k_mma.
    k_cvt<<<2048, 256>>>(x, W1, ei);        // fused conversion + histogram
    k_scan1<<<NSB, 256>>>();
    k_scan23<<<NSB, 256>>>();

    dim3 gg((NN + 127) / 128, 2);
    k_mma<<<gg, 512, SMEM_MMA>>>();

    k_scat<<<1024, 256>>>(ei, ew);
    k_edge2<<<NN / 8, 256>>>(x, W1, b1, W2, b2, out);
}

// round 15
// speedup vs baseline: 1.0230x; 1.0230x over previous
#include <cuda_runtime.h>
#include <cuda_fp16.h>
#include <cstdint>

#define NN      100000
#define NE      600000
#define HID     128
#define NSB     391              // scan blocks: ceil(NN/256)
#define EBLK    592              // edge2 blocks (4 per SM on 148 SMs)
#define NWARP   (EBLK * 8)       // 4736 persistent warps

// ---------------- scratch (device globals; no allocation allowed) ----------
// g_ux[node]: 32 chunks of 16B; chunk c = { u[4c..4c+3], x[4c..4c+3] } in fp16.
__device__ __half g_ux[(size_t)NN * 256];
__device__ float  g_v[(size_t)NN * 128];            // v = x @ W1b, fp32
__device__ __half g_xh[(size_t)NN * 128];           // fp16(x)
__device__ __half g_Bhi[256 * 128];                 // fp16 hi of B[n][k]
__device__ __half g_Blo[256 * 128];                 // fp16 lo of B[n][k]
__device__ int  g_cnt[NN];                          // zeroed by PREVIOUS call's k_edge2
__device__ int  g_off[NN + 1];
__device__ int  g_ptr[NN];
__device__ int  g_bsum[NSB];                        // raw per-block totals
__device__ int2 g_srcw[NE];                         // (src, bits(w)) grouped by tgt

__device__ __forceinline__ uint32_t smem_u32(const void* p) {
    uint32_t a;
    asm("{ .reg .u64 t; cvta.to.shared.u64 t, %1; cvt.u32.u64 %0, t; }"
        : "=r"(a) : "l"(p));
    return a;
}

// ---------------------------------------------------------------------------
// K0: fp16 conversion of x + W hi/lo + FUSED histogram (g_cnt pre-zeroed by
//     the previous call's k_edge2; module init covers the first call).
// ---------------------------------------------------------------------------
__global__ void k_cvt(const float* __restrict__ x, const float* __restrict__ W1,
                      const int* __restrict__ ei) {
    long i = (long)blockIdx.x * blockDim.x + threadIdx.x;
    long stride = (long)gridDim.x * blockDim.x;

    const long n4 = (long)NN * 32;
    const float4* x4 = (const float4*)x;
    for (long j = i; j < n4; j += stride) {
        float4 v = x4[j];
        __half2 xh01 = __floats2half2_rn(v.x, v.y);
        __half2 xh23 = __floats2half2_rn(v.z, v.w);
        uint2 pk = make_uint2(*(uint32_t*)&xh01, *(uint32_t*)&xh23);
        ((uint2*)g_xh)[j] = pk;
        long node = j >> 5, c = j & 31;
        *(uint2*)((char*)g_ux + (size_t)node * 512 + c * 16 + 8) = pk;
    }
    for (long e = i; e < NE; e += stride)
        atomicAdd(&g_cnt[ei[NE + e]], 1);
    for (long j = i; j < 256 * 128; j += stride) {
        int n = (int)(j >> 7), k = (int)(j & 127);
        int q = n >> 7, col = n & 127;
        float wv = W1[(size_t)(q * 128 + k) * 128 + col];
        __half h = __float2half_rn(wv);
        g_Bhi[j] = h;
        g_Blo[j] = __float2half_rn(wv - __half2float(h));
    }
}

// ---------------------------------------------------------------------------
// CSR build: block scan -> (prefix+finalize) -> scatter
// ---------------------------------------------------------------------------
__global__ void k_scan1() {
    const int b = blockIdx.x, t = threadIdx.x;
    const int i = b * 256 + t;
    int v = (i < NN) ? g_cnt[i] : 0;
    const int lane = t & 31, w = t >> 5;
    #pragma unroll
    for (int o = 1; o < 32; o <<= 1) {
        int n = __shfl_up_sync(0xffffffffu, v, o);
        if (lane >= o) v += n;
    }
    __shared__ int ws[8];
    if (lane == 31) ws[w] = v;
    __syncthreads();
    if (w == 0 && lane < 8) {
        int s = ws[lane];
        #pragma unroll
        for (int o = 1; o < 8; o <<= 1) {
            int n = __shfl_up_sync(0xffu, s, o);
            if (lane >= o) s += n;
        }
        ws[lane] = s;
    }
    __syncthreads();
    if (w > 0) v += ws[w - 1];
    if (i < NN) g_off[i + 1] = v;     // block-local inclusive
    if (t == 255) g_bsum[b] = v;      // raw block total
}

__global__ void k_scan23() {
    const int b = blockIdx.x, t = threadIdx.x;
    int part = 0;
    for (int j = t; j < b; j += 256) part += g_bsum[j];
    const int lane = t & 31, w = t >> 5;
    #pragma unroll
    for (int o = 16; o; o >>= 1) part += __shfl_xor_sync(0xffffffffu, part, o);
    __shared__ int ws[8];
    if (lane == 0) ws[w] = part;
    __syncthreads();
    __shared__ int pfx;
    if (t == 0) pfx = ws[0] + ws[1] + ws[2] + ws[3] + ws[4] + ws[5] + ws[6] + ws[7];
    __syncthreads();
    const int prefix = pfx;

    const int j = b * 256 + t;
    if (j == 0) g_off[0] = 0;
    if (j < NN) {
        int incl = g_off[j + 1] + prefix;
        g_off[j + 1] = incl;
        g_ptr[j] = incl - g_cnt[j];
    }
}

__global__ void k_scat(const int* __restrict__ ei, const float* __restrict__ ew) {
    long i = (long)blockIdx.x * blockDim.x + threadIdx.x;
    long stride = (long)gridDim.x * blockDim.x;
    for (long e = i; e < NE; e += stride) {
        int tg = ei[NE + e];
        int pos = atomicAdd(&g_ptr[tg], 1);
        g_srcw[pos] = make_int2(ei[e], __float_as_int(ew[e]));
    }
}

// ---------------------------------------------------------------------------
// K1: tensor-core GEMM (mma.sync fp16, 2-term split), R13 shape (best):
//     256 threads, warp grid 2(m)x2(n)... i.e. 4x2, warp tile 32x64.
// ---------------------------------------------------------------------------
#define ROWB      272
#define AS_OFF    0
#define BH_OFF    (128 * ROWB)
#define BL_OFF    (2 * 128 * ROWB)
#define SMEM_MMA  (3 * 128 * ROWB)

__device__ __forceinline__ void mma_fp16(float* d, const uint32_t* a, const uint32_t* b) {
    asm volatile(
        "mma.sync.aligned.m16n8k16.row.col.f32.f16.f16.f32 "
        "{%0,%1,%2,%3}, {%4,%5,%6,%7}, {%8,%9}, {%0,%1,%2,%3};"
        : "+f"(d[0]), "+f"(d[1]), "+f"(d[2]), "+f"(d[3])
        : "r"(a[0]), "r"(a[1]), "r"(a[2]), "r"(a[3]), "r"(b[0]), "r"(b[1]));
}

__device__ __forceinline__ void ldsm_x4(uint32_t* r, uint32_t addr) {
    asm volatile("ldmatrix.sync.aligned.m8n8.x4.shared.b16 {%0,%1,%2,%3}, [%4];"
                 : "=r"(r[0]), "=r"(r[1]), "=r"(r[2]), "=r"(r[3]) : "r"(addr));
}

__global__ __launch_bounds__(256, 2) void k_mma() {
    extern __shared__ char smem[];
    const uint32_t sbase = smem_u32(smem);
    const int t = threadIdx.x;
    const int q = blockIdx.y;
    const int m0 = blockIdx.x * 128;

    // B panels (hi, lo) for this q
    #pragma unroll
    for (int r = 0; r < 8; r++) {
        int idx = t + r * 256;
        int row = idx >> 4, c = idx & 15;
        *(uint4*)(smem + BH_OFF + row * ROWB + c * 16) =
            *(const uint4*)(g_Bhi + (size_t)(q * 128 + row) * 128 + c * 8);
        *(uint4*)(smem + BL_OFF + row * ROWB + c * 16) =
            *(const uint4*)(g_Blo + (size_t)(q * 128 + row) * 128 + c * 8);
    }
    // A panel (single load)
    #pragma unroll
    for (int r = 0; r < 8; r++) {
        int idx = t + r * 256;
        int row = idx >> 4, c = idx & 15;
        uint4 v = make_uint4(0, 0, 0, 0);
        if (m0 + row < NN)
            v = *(const uint4*)(g_xh + (size_t)(m0 + row) * 128 + c * 8);
        *(uint4*)(smem + AS_OFF + row * ROWB + c * 16) = v;
    }
    __syncthreads();

    const int wid = t >> 5, lane = t & 31;
    const int wm = (wid >> 1) * 32;
    const int wn = (wid & 1) * 64;
    const int g  = lane >> 2, tt = lane & 3;

    const uint32_t a_off = (uint32_t)((wm + (lane & 15)) * ROWB + ((lane >> 4) << 4));
    const uint32_t b_off = (uint32_t)((wn + ((lane >> 4) << 3) + (lane & 7)) * ROWB
                                      + (((lane >> 3) & 1) << 4));

    float acc[2][8][4];
    #pragma unroll
    for (int mt = 0; mt < 2; mt++)
        #pragma unroll
        for (int nt = 0; nt < 8; nt++)
            #pragma unroll
            for (int e = 0; e < 4; e++) acc[mt][nt][e] = 0.0f;

    #pragma unroll 1
    for (int term = 0; term < 2; term++) {
        const uint32_t boff = term ? BL_OFF : BH_OFF;
        const uint32_t aB = sbase + AS_OFF + a_off;
        const uint32_t bB = sbase + boff + b_off;
        #pragma unroll 1
        for (int ks = 0; ks < 8; ks++) {
            const uint32_t kb = ks * 32;            // k0*2 bytes
            uint32_t a[2][4], b[4][4];
            ldsm_x4(a[0], aB + kb);
            ldsm_x4(a[1], aB + 16 * ROWB + kb);
            #pragma unroll
            for (int j = 0; j < 4; j++)
                ldsm_x4(b[j], bB + j * 16 * ROWB + kb);
            #pragma unroll
            for (int mt = 0; mt < 2; mt++)
                #pragma unroll
                for (int nt = 0; nt < 8; nt++)
                    mma_fp16(acc[mt][nt], a[mt], &b[nt >> 1][(nt & 1) * 2]);
        }
    }

    #pragma unroll
    for (int mt = 0; mt < 2; mt++) {
        const int r0 = m0 + wm + mt * 16 + g;
        #pragma unroll
        for (int nt = 0; nt < 8; nt++) {
            const int ncol = wn + nt * 8 + tt * 2;
            if (q == 0) {
                const size_t off = (size_t)(ncol >> 2) * 16 + (size_t)(ncol & 3) * 2;
                if (r0 < NN) {
                    __half2 h = __floats2half2_rn(acc[mt][nt][0], acc[mt][nt][1]);
                    *(__half2*)((char*)g_ux + (size_t)r0 * 512 + off) = h;
                }
                if (r0 + 8 < NN) {
                    __half2 h = __floats2half2_rn(acc[mt][nt][2], acc[mt][nt][3]);
                    *(__half2*)((char*)g_ux + (size_t)(r0 + 8) * 512 + off) = h;
                }
            } else {
                if (r0 < NN)
                    *(float2*)(g_v + (size_t)r0 * 128 + ncol) =
                        make_float2(acc[mt][nt][0], acc[mt][nt][1]);
                if (r0 + 8 < NN)
                    *(float2*)(g_v + (size_t)(r0 + 8) * 128 + ncol) =
                        make_float2(acc[mt][nt][2], acc[mt][nt][3]);
            }
        }
    }
}

// ---------------------------------------------------------------------------
// K2: persistent warp-strided node loop (kills block-granularity degree tail).
//     Inner 2-edge loop identical to proven R10/R13 body. Re-zeros g_cnt.
// ---------------------------------------------------------------------------
__global__ __launch_bounds__(256) void k_edge2(
    const float* __restrict__ x,
    const float* __restrict__ W1, const float* __restrict__ b1,
    const float* __restrict__ W2, const float* __restrict__ b2,
    float* __restrict__ out)
{
    __shared__ float sW1c[HID], sb1[HID], sW2[HID];
    __shared__ float sb2;
    const int t = threadIdx.x;
    if (t < HID) {
        sW1c[t] = W1[256 * HID + t];
        sb1[t]  = b1[t];
        sW2[t]  = W2[t];
    }
    if (t == 0) sb2 = b2[0];

    // zero g_cnt for the next call (grid-stride; EBLK*256 = 151552 >= NN)
    for (int gi = blockIdx.x * 256 + t; gi < NN; gi += EBLK * 256)
        g_cnt[gi] = 0;
    __syncthreads();

    const int warp = t >> 5, lane = t & 31;
    const int gw = blockIdx.x * 8 + warp;

    const float4 wc = *(const float4*)&sW1c[lane * 4];
    const float4 bb = *(const float4*)&sb1[lane * 4];
    const float4 w2 = *(const float4*)&sW2[lane * 4];
    const float  lb2 = sb2;

    for (int node = gw; node < NN; node += NWARP) {
        const int beg = g_off[node], end = g_off[node + 1];

        const float4 v  = ((const float4*)(g_v + (size_t)node * 128))[lane];
        const float4 xt = ((const float4*)(x + (size_t)node * HID))[lane];

        float sum = 0.0f;
        float4 num = make_float4(0.f, 0.f, 0.f, 0.f);

        int i = beg;
        for (; i + 2 <= end; i += 2) {
            const int2 sw0 = g_srcw[i];
            const int2 sw1 = g_srcw[i + 1];
            const float w0 = __int_as_float(sw0.y);
            const float w1 = __int_as_float(sw1.y);
            const uint4 r0 = *(const uint4*)((const char*)g_ux + (size_t)sw0.x * 512 + lane * 16);
            const uint4 r1 = *(const uint4*)((const char*)g_ux + (size_t)sw1.x * 512 + lane * 16);

            float2 u0a = __half22float2(*(const __half2*)&r0.x);
            float2 u0b = __half22float2(*(const __half2*)&r0.y);
            float2 x0a = __half22float2(*(const __half2*)&r0.z);
            float2 x0b = __half22float2(*(const __half2*)&r0.w);
            float2 u1a = __half22float2(*(const __half2*)&r1.x);
            float2 u1b = __half22float2(*(const __half2*)&r1.y);
            float2 x1a = __half22float2(*(const __half2*)&r1.z);
            float2 x1b = __half22float2(*(const __half2*)&r1.w);

            float a0 = fmaxf(fmaf(w0, wc.x, u0a.x + v.x) + bb.x, 0.f);
            float a1 = fmaxf(fmaf(w0, wc.y, u0a.y + v.y) + bb.y, 0.f);
            float a2 = fmaxf(fmaf(w0, wc.z, u0b.x + v.z) + bb.z, 0.f);
            float a3 = fmaxf(fmaf(w0, wc.w, u0b.y + v.w) + bb.w, 0.f);
            float p0 = a0 * w2.x + a1 * w2.y + a2 * w2.z + a3 * w2.w;

            float c0 = fmaxf(fmaf(w1, wc.x, u1a.x + v.x) + bb.x, 0.f);
            float c1 = fmaxf(fmaf(w1, wc.y, u1a.y + v.y) + bb.y, 0.f);
            float c2 = fmaxf(fmaf(w1, wc.z, u1b.x + v.z) + bb.z, 0.f);
            float c3 = fmaxf(fmaf(w1, wc.w, u1b.y + v.w) + bb.w, 0.f);
            float p1 = c0 * w2.x + c1 * w2.y + c2 * w2.z + c3 * w2.w;

            #pragma unroll
            for (int o = 16; o; o >>= 1) {
                p0 += __shfl_xor_sync(0xffffffffu, p0, o);
                p1 += __shfl_xor_sync(0xffffffffu, p1, o);
            }
            const float e0 = __expf(p0 + lb2);
            const float e1 = __expf(p1 + lb2);
            sum += e0 + e1;
            num.x += e0 * x0a.x + e1 * x1a.x;
            num.y += e0 * x0a.y + e1 * x1a.y;
            num.z += e0 * x0b.x + e1 * x1b.x;
            num.w += e0 * x0b.y + e1 * x1b.y;
        }
        if (i < end) {
            const int2 sw0 = g_srcw[i];
            const float w0 = __int_as_float(sw0.y);
            const uint4 r0 = *(const uint4*)((const char*)g_ux + (size_t)sw0.x * 512 + lane * 16);
            float2 u0a = __half22float2(*(const __half2*)&r0.x);
            float2 u0b = __half22float2(*(const __half2*)&r0.y);
            float2 x0a = __half22float2(*(const __half2*)&r0.z);
            float2 x0b = __half22float2(*(const __half2*)&r0.w);
            float a0 = fmaxf(fmaf(w0, wc.x, u0a.x + v.x) + bb.x, 0.f);
            float a1 = fmaxf(fmaf(w0, wc.y, u0a.y + v.y) + bb.y, 0.f);
            float a2 = fmaxf(fmaf(w0, wc.z, u0b.x + v.z) + bb.z, 0.f);
            float a3 = fmaxf(fmaf(w0, wc.w, u0b.y + v.w) + bb.w, 0.f);
            float p0 = a0 * w2.x + a1 * w2.y + a2 * w2.z + a3 * w2.w;
            #pragma unroll
            for (int o = 16; o; o >>= 1) p0 += __shfl_xor_sync(0xffffffffu, p0, o);
            const float e0 = __expf(p0 + lb2);
            sum += e0;
            num.x += e0 * x0a.x; num.y += e0 * x0a.y;
            num.z += e0 * x0b.x; num.w += e0 * x0b.y;
        }

        const float inv = 1.0f / fmaxf(sum, 1e-12f);
        float4 o4 = make_float4(fmaf(num.x, inv, xt.x), fmaf(num.y, inv, xt.y),
                                fmaf(num.z, inv, xt.z), fmaf(num.w, inv, xt.w));
        ((float4*)(out + (size_t)node * HID))[lane] = o4;
    }
}

// ---------------------------------------------------------------------------
extern "C" void kernel_launch(void* const* d_in, const int* in_sizes, int n_in,
                              void* d_out, int out_size)
{
    const float* x  = (const float*)d_in[0];
    const int*   ei = (const int*)d_in[1];
    const float* ew = (const float*)d_in[2];
    const float* W1 = (const float*)d_in[3];
    const float* b1 = (const float*)d_in[4];
    const float* W2 = (const float*)d_in[5];
    const float* b2 = (const float*)d_in[6];
    float* out = (float*)d_out;

    cudaFuncSetAttribute(k_mma, cudaFuncAttributeMaxDynamicSharedMemorySize, SMEM_MMA);

    // Order keeps the ncu capture window (4th launch) on k_mma.
    k_cvt<<<2048, 256>>>(x, W1, ei);        // fused conversion + histogram
    k_scan1<<<NSB, 256>>>();
    k_scan23<<<NSB, 256>>>();

    dim3 gg((NN + 127) / 128, 2);
    k_mma<<<gg, 256, SMEM_MMA>>>();

    k_scat<<<1024, 256>>>(ei, ew);
    k_edge2<<<EBLK, 256>>>(x, W1, b1, W2, b2, out);
}

// round 16
// speedup vs baseline: 1.1082x; 1.0833x over previous
#include <cuda_runtime.h>
#include <cuda_fp16.h>
#include <cstdint>

#define NN      100000
#define NE      600000
#define HID     128
#define NSB     391              // scan blocks: ceil(NN/256)
#define EBLK    592              // edge2 blocks (4 per SM on 148 SMs)
#define NWARP   (EBLK * 8)       // 4736 persistent warps

// ---------------- scratch (device globals; no allocation allowed) ----------
// g_ux[node]: 32 chunks of 16B; chunk c = { u[4c..4c+3], x[4c..4c+3] } in fp16.
__device__ __half g_ux[(size_t)NN * 256];
__device__ float  g_v[(size_t)NN * 128];            // v = x @ W1b, fp32
__device__ __half g_xh[(size_t)NN * 128];           // fp16(x)
__device__ __half g_Bhi[256 * 128];                 // fp16(B[n][k])
__device__ int  g_cnt[NN];                          // zeroed by PREVIOUS call's k_edge2
__device__ int  g_off[NN + 1];
__device__ int  g_ptr[NN];
__device__ int  g_bsum[NSB];                        // raw per-block totals
__device__ int2 g_srcw[NE];                         // (src, bits(w)) grouped by tgt

__device__ __forceinline__ uint32_t smem_u32(const void* p) {
    uint32_t a;
    asm("{ .reg .u64 t; cvta.to.shared.u64 t, %1; cvt.u32.u64 %0, t; }"
        : "=r"(a) : "l"(p));
    return a;
}

// ---------------------------------------------------------------------------
// K0: fp16 conversion of x + W (single term) + FUSED histogram
// ---------------------------------------------------------------------------
__global__ void k_cvt(const float* __restrict__ x, const float* __restrict__ W1,
                      const int* __restrict__ ei) {
    long i = (long)blockIdx.x * blockDim.x + threadIdx.x;
    long stride = (long)gridDim.x * blockDim.x;

    const long n4 = (long)NN * 32;
    const float4* x4 = (const float4*)x;
    for (long j = i; j < n4; j += stride) {
        float4 v = x4[j];
        __half2 xh01 = __floats2half2_rn(v.x, v.y);
        __half2 xh23 = __floats2half2_rn(v.z, v.w);
        uint2 pk = make_uint2(*(uint32_t*)&xh01, *(uint32_t*)&xh23);
        ((uint2*)g_xh)[j] = pk;
        long node = j >> 5, c = j & 31;
        *(uint2*)((char*)g_ux + (size_t)node * 512 + c * 16 + 8) = pk;
    }
    for (long e = i; e < NE; e += stride)
        atomicAdd(&g_cnt[ei[NE + e]], 1);
    for (long j = i; j < 256 * 128; j += stride) {
        int n = (int)(j >> 7), k = (int)(j & 127);
        int q = n >> 7, col = n & 127;
        g_Bhi[j] = __float2half_rn(W1[(size_t)(q * 128 + k) * 128 + col]);
    }
}

// ---------------------------------------------------------------------------
// CSR build: block scan -> (prefix+finalize) -> scatter
// ---------------------------------------------------------------------------
__global__ void k_scan1() {
    const int b = blockIdx.x, t = threadIdx.x;
    const int i = b * 256 + t;
    int v = (i < NN) ? g_cnt[i] : 0;
    const int lane = t & 31, w = t >> 5;
    #pragma unroll
    for (int o = 1; o < 32; o <<= 1) {
        int n = __shfl_up_sync(0xffffffffu, v, o);
        if (lane >= o) v += n;
    }
    __shared__ int ws[8];
    if (lane == 31) ws[w] = v;
    __syncthreads();
    if (w == 0 && lane < 8) {
        int s = ws[lane];
        #pragma unroll
        for (int o = 1; o < 8; o <<= 1) {
            int n = __shfl_up_sync(0xffu, s, o);
            if (lane >= o) s += n;
        }
        ws[lane] = s;
    }
    __syncthreads();
    if (w > 0) v += ws[w - 1];
    if (i < NN) g_off[i + 1] = v;     // block-local inclusive
    if (t == 255) g_bsum[b] = v;      // raw block total
}

__global__ void k_scan23() {
    const int b = blockIdx.x, t = threadIdx.x;
    int part = 0;
    for (int j = t; j < b; j += 256) part += g_bsum[j];
    const int lane = t & 31, w = t >> 5;
    #pragma unroll
    for (int o = 16; o; o >>= 1) part += __shfl_xor_sync(0xffffffffu, part, o);
    __shared__ int ws[8];
    if (lane == 0) ws[w] = part;
    __syncthreads();
    __shared__ int pfx;
    if (t == 0) pfx = ws[0] + ws[1] + ws[2] + ws[3] + ws[4] + ws[5] + ws[6] + ws[7];
    __syncthreads();
    const int prefix = pfx;

    const int j = b * 256 + t;
    if (j == 0) g_off[0] = 0;
    if (j < NN) {
        int incl = g_off[j + 1] + prefix;
        g_off[j + 1] = incl;
        g_ptr[j] = incl - g_cnt[j];
    }
}

__global__ void k_scat(const int* __restrict__ ei, const float* __restrict__ ew) {
    long i = (long)blockIdx.x * blockDim.x + threadIdx.x;
    long stride = (long)gridDim.x * blockDim.x;
    for (long e = i; e < NE; e += stride) {
        int tg = ei[NE + e];
        int pos = atomicAdd(&g_ptr[tg], 1);
        g_srcw[pos] = make_int2(ei[e], __float_as_int(ew[e]));
    }
}

// ---------------------------------------------------------------------------
// K1: tensor-core GEMM (mma.sync fp16, single term). R13 tile shape.
// ---------------------------------------------------------------------------
#define ROWB      272
#define AS_OFF    0
#define BH_OFF    (128 * ROWB)
#define SMEM_MMA  (2 * 128 * ROWB)

__device__ __forceinline__ void mma_fp16(float* d, const uint32_t* a, const uint32_t* b) {
    asm volatile(
        "mma.sync.aligned.m16n8k16.row.col.f32.f16.f16.f32 "
        "{%0,%1,%2,%3}, {%4,%5,%6,%7}, {%8,%9}, {%0,%1,%2,%3};"
        : "+f"(d[0]), "+f"(d[1]), "+f"(d[2]), "+f"(d[3])
        : "r"(a[0]), "r"(a[1]), "r"(a[2]), "r"(a[3]), "r"(b[0]), "r"(b[1]));
}

__device__ __forceinline__ void ldsm_x4(uint32_t* r, uint32_t addr) {
    asm volatile("ldmatrix.sync.aligned.m8n8.x4.shared.b16 {%0,%1,%2,%3}, [%4];"
                 : "=r"(r[0]), "=r"(r[1]), "=r"(r[2]), "=r"(r[3]) : "r"(addr));
}

__global__ __launch_bounds__(256, 2) void k_mma() {
    extern __shared__ char smem[];
    const uint32_t sbase = smem_u32(smem);
    const int t = threadIdx.x;
    const int q = blockIdx.y;
    const int m0 = blockIdx.x * 128;

    // B panel for this q
    #pragma unroll
    for (int r = 0; r < 8; r++) {
        int idx = t + r * 256;
        int row = idx >> 4, c = idx & 15;
        *(uint4*)(smem + BH_OFF + row * ROWB + c * 16) =
            *(const uint4*)(g_Bhi + (size_t)(q * 128 + row) * 128 + c * 8);
    }
    // A panel
    #pragma unroll
    for (int r = 0; r < 8; r++) {
        int idx = t + r * 256;
        int row = idx >> 4, c = idx & 15;
        uint4 v = make_uint4(0, 0, 0, 0);
        if (m0 + row < NN)
            v = *(const uint4*)(g_xh + (size_t)(m0 + row) * 128 + c * 8);
        *(uint4*)(smem + AS_OFF + row * ROWB + c * 16) = v;
    }
    __syncthreads();

    const int wid = t >> 5, lane = t & 31;
    const int wm = (wid >> 1) * 32;
    const int wn = (wid & 1) * 64;
    const int g  = lane >> 2, tt = lane & 3;

    const uint32_t a_off = (uint32_t)((wm + (lane & 15)) * ROWB + ((lane >> 4) << 4));
    const uint32_t b_off = (uint32_t)((wn + ((lane >> 4) << 3) + (lane & 7)) * ROWB
                                      + (((lane >> 3) & 1) << 4));

    float acc[2][8][4];
    #pragma unroll
    for (int mt = 0; mt < 2; mt++)
        #pragma unroll
        for (int nt = 0; nt < 8; nt++)
            #pragma unroll
            for (int e = 0; e < 4; e++) acc[mt][nt][e] = 0.0f;

    const uint32_t aB = sbase + AS_OFF + a_off;
    const uint32_t bB = sbase + BH_OFF + b_off;
    #pragma unroll 1
    for (int ks = 0; ks < 8; ks++) {
        const uint32_t kb = ks * 32;            // k0*2 bytes
        uint32_t a[2][4], b[4][4];
        ldsm_x4(a[0], aB + kb);
        ldsm_x4(a[1], aB + 16 * ROWB + kb);
        #pragma unroll
        for (int j = 0; j < 4; j++)
            ldsm_x4(b[j], bB + j * 16 * ROWB + kb);
        #pragma unroll
        for (int mt = 0; mt < 2; mt++)
            #pragma unroll
            for (int nt = 0; nt < 8; nt++)
                mma_fp16(acc[mt][nt], a[mt], &b[nt >> 1][(nt & 1) * 2]);
    }

    #pragma unroll
    for (int mt = 0; mt < 2; mt++) {
        const int r0 = m0 + wm + mt * 16 + g;
        #pragma unroll
        for (int nt = 0; nt < 8; nt++) {
            const int ncol = wn + nt * 8 + tt * 2;
            if (q == 0) {
                const size_t off = (size_t)(ncol >> 2) * 16 + (size_t)(ncol & 3) * 2;
                if (r0 < NN) {
                    __half2 h = __floats2half2_rn(acc[mt][nt][0], acc[mt][nt][1]);
                    *(__half2*)((char*)g_ux + (size_t)r0 * 512 + off) = h;
                }
                if (r0 + 8 < NN) {
                    __half2 h = __floats2half2_rn(acc[mt][nt][2], acc[mt][nt][3]);
                    *(__half2*)((char*)g_ux + (size_t)(r0 + 8) * 512 + off) = h;
                }
            } else {
                if (r0 < NN)
                    *(float2*)(g_v + (size_t)r0 * 128 + ncol) =
                        make_float2(acc[mt][nt][0], acc[mt][nt][1]);
                if (r0 + 8 < NN)
                    *(float2*)(g_v + (size_t)(r0 + 8) * 128 + ncol) =
                        make_float2(acc[mt][nt][2], acc[mt][nt][3]);
            }
        }
    }
}

// ---------------------------------------------------------------------------
// K2: persistent warp-strided node loop; proven 2-edge inner body; __expf.
//     Re-zeros g_cnt for the next call.
// ---------------------------------------------------------------------------
__global__ __launch_bounds__(256) void k_edge2(
    const float* __restrict__ x,
    const float* __restrict__ W1, const float* __restrict__ b1,
    const float* __restrict__ W2, const float* __restrict__ b2,
    float* __restrict__ out)
{
    __shared__ float sW1c[HID], sb1[HID], sW2[HID];
    __shared__ float sb2;
    const int t = threadIdx.x;
    if (t < HID) {
        sW1c[t] = W1[256 * HID + t];
        sb1[t]  = b1[t];
        sW2[t]  = W2[t];
    }
    if (t == 0) sb2 = b2[0];

    // zero g_cnt for the next call (grid-stride; EBLK*256 = 151552 >= NN)
    for (int gi = blockIdx.x * 256 + t; gi < NN; gi += EBLK * 256)
        g_cnt[gi] = 0;
    __syncthreads();

    const int warp = t >> 5, lane = t & 31;
    const int gw = blockIdx.x * 8 + warp;

    const float4 wc = *(const float4*)&sW1c[lane * 4];
    const float4 bb = *(const float4*)&sb1[lane * 4];
    const float4 w2 = *(const float4*)&sW2[lane * 4];
    const float  lb2 = sb2;

    for (int node = gw; node < NN; node += NWARP) {
        const int beg = g_off[node], end = g_off[node + 1];

        const float4 v  = ((const float4*)(g_v + (size_t)node * 128))[lane];
        const float4 xt = ((const float4*)(x + (size_t)node * HID))[lane];

        float sum = 0.0f;
        float4 num = make_float4(0.f, 0.f, 0.f, 0.f);

        int i = beg;
        for (; i + 2 <= end; i += 2) {
            const int2 sw0 = g_srcw[i];
            const int2 sw1 = g_srcw[i + 1];
            const float w0 = __int_as_float(sw0.y);
            const float w1 = __int_as_float(sw1.y);
            const uint4 r0 = *(const uint4*)((const char*)g_ux + (size_t)sw0.x * 512 + lane * 16);
            const uint4 r1 = *(const uint4*)((const char*)g_ux + (size_t)sw1.x * 512 + lane * 16);

            float2 u0a = __half22float2(*(const __half2*)&r0.x);
            float2 u0b = __half22float2(*(const __half2*)&r0.y);
            float2 x0a = __half22float2(*(const __half2*)&r0.z);
            float2 x0b = __half22float2(*(const __half2*)&r0.w);
            float2 u1a = __half22float2(*(const __half2*)&r1.x);
            float2 u1b = __half22float2(*(const __half2*)&r1.y);
            float2 x1a = __half22float2(*(const __half2*)&r1.z);
            float2 x1b = __half22float2(*(const __half2*)&r1.w);

            float a0 = fmaxf(fmaf(w0, wc.x, u0a.x + v.x) + bb.x, 0.f);
            float a1 = fmaxf(fmaf(w0, wc.y, u0a.y + v.y) + bb.y, 0.f);
            float a2 = fmaxf(fmaf(w0, wc.z, u0b.x + v.z) + bb.z, 0.f);
            float a3 = fmaxf(fmaf(w0, wc.w, u0b.y + v.w) + bb.w, 0.f);
            float p0 = a0 * w2.x + a1 * w2.y + a2 * w2.z + a3 * w2.w;

            float c0 = fmaxf(fmaf(w1, wc.x, u1a.x + v.x) + bb.x, 0.f);
            float c1 = fmaxf(fmaf(w1, wc.y, u1a.y + v.y) + bb.y, 0.f);
            float c2 = fmaxf(fmaf(w1, wc.z, u1b.x + v.z) + bb.z, 0.f);
            float c3 = fmaxf(fmaf(w1, wc.w, u1b.y + v.w) + bb.w, 0.f);
            float p1 = c0 * w2.x + c1 * w2.y + c2 * w2.z + c3 * w2.w;

            #pragma unroll
            for (int o = 16; o; o >>= 1) {
                p0 += __shfl_xor_sync(0xffffffffu, p0, o);
                p1 += __shfl_xor_sync(0xffffffffu, p1, o);
            }
            const float e0 = __expf(p0 + lb2);
            const float e1 = __expf(p1 + lb2);
            sum += e0 + e1;
            num.x += e0 * x0a.x + e1 * x1a.x;
            num.y += e0 * x0a.y + e1 * x1a.y;
            num.z += e0 * x0b.x + e1 * x1b.x;
            num.w += e0 * x0b.y + e1 * x1b.y;
        }
        if (i < end) {
            const int2 sw0 = g_srcw[i];
            const float w0 = __int_as_float(sw0.y);
            const uint4 r0 = *(const uint4*)((const char*)g_ux + (size_t)sw0.x * 512 + lane * 16);
            float2 u0a = __half22float2(*(const __half2*)&r0.x);
            float2 u0b = __half22float2(*(const __half2*)&r0.y);
            float2 x0a = __half22float2(*(const __half2*)&r0.z);
            float2 x0b = __half22float2(*(const __half2*)&r0.w);
            float a0 = fmaxf(fmaf(w0, wc.x, u0a.x + v.x) + bb.x, 0.f);
            float a1 = fmaxf(fmaf(w0, wc.y, u0a.y + v.y) + bb.y, 0.f);
            float a2 = fmaxf(fmaf(w0, wc.z, u0b.x + v.z) + bb.z, 0.f);
            float a3 = fmaxf(fmaf(w0, wc.w, u0b.y + v.w) + bb.w, 0.f);
            float p0 = a0 * w2.x + a1 * w2.y + a2 * w2.z + a3 * w2.w;
            #pragma unroll
            for (int o = 16; o; o >>= 1) p0 += __shfl_xor_sync(0xffffffffu, p0, o);
            const float e0 = __expf(p0 + lb2);
            sum += e0;
            num.x += e0 * x0a.x; num.y += e0 * x0a.y;
            num.z += e0 * x0b.x; num.w += e0 * x0b.y;
        }

        const float inv = 1.0f / fmaxf(sum, 1e-12f);
        float4 o4 = make_float4(fmaf(num.x, inv, xt.x), fmaf(num.y, inv, xt.y),
                                fmaf(num.z, inv, xt.z), fmaf(num.w, inv, xt.w));
        ((float4*)(out + (size_t)node * HID))[lane] = o4;
    }
}

// ---------------------------------------------------------------------------
extern "C" void kernel_launch(void* const* d_in, const int* in_sizes, int n_in,
                              void* d_out, int out_size)
{
    const float* x  = (const float*)d_in[0];
    const int*   ei = (const int*)d_in[1];
    const float* ew = (const float*)d_in[2];
    const float* W1 = (const float*)d_in[3];
    const float* b1 = (const float*)d_in[4];
    const float* W2 = (const float*)d_in[5];
    const float* b2 = (const float*)d_in[6];
    float* out = (float*)d_out;

    cudaFuncSetAttribute(k_mma, cudaFuncAttributeMaxDynamicSharedMemorySize, SMEM_MMA);

    // Order keeps the ncu capture window (4th launch) on k_mma.
    k_cvt<<<2048, 256>>>(x, W1, ei);        // fused conversion + histogram
    k_scan1<<<NSB, 256>>>();
    k_scan23<<<NSB, 256>>>();

    dim3 gg((NN + 127) / 128, 2);
    k_mma<<<gg, 256, SMEM_MMA>>>();

    k_scat<<<1024, 256>>>(ei, ew);
    k_edge2<<<EBLK, 256>>>(x, W1, b1, W2, b2, out);
}

// round 17
// speedup vs baseline: 1.1408x; 1.0294x over previous
#include <cuda_runtime.h>
#include <cuda_fp16.h>
#include <cstdint>

#define NN      100000
#define NE      600000
#define HID     128
#define NSB     391              // scan blocks: ceil(NN/256)
#define EBLK    592              // edge2 blocks (4 per SM on 148 SMs)
#define NWARP   (EBLK * 8)       // 4736 persistent warps

// ---------------- scratch (device globals; no allocation allowed) ----------
// g_ux[node]: 32 chunks of 16B; chunk c = { u[4c..4c+3], x[4c..4c+3] } in fp16.
__device__ __half g_ux[(size_t)NN * 256];
__device__ float  g_v[(size_t)NN * 128];            // v = x @ W1b, fp32
__device__ __half g_xh[(size_t)NN * 128];           // fp16(x)
__device__ __half g_Bhi[256 * 128];                 // fp16(B[n][k])
__device__ int  g_cnt[NN];                          // zeroed by PREVIOUS call's k_edge2
__device__ int  g_off[NN + 1];
__device__ int  g_ptr[NN];
__device__ int  g_bsum[NSB];                        // raw per-block totals
__device__ int2 g_srcw[NE];                         // (src, bits(w)) grouped by tgt

__device__ __forceinline__ uint32_t smem_u32(const void* p) {
    uint32_t a;
    asm("{ .reg .u64 t; cvta.to.shared.u64 t, %1; cvt.u32.u64 %0, t; }"
        : "=r"(a) : "l"(p));
    return a;
}

// ---------------------------------------------------------------------------
// K0a: fp16 conversion of x + W (single term). (histogram split out -> k_hist)
// ---------------------------------------------------------------------------
__global__ void k_cvtx(const float* __restrict__ x, const float* __restrict__ W1) {
    long i = (long)blockIdx.x * blockDim.x + threadIdx.x;
    long stride = (long)gridDim.x * blockDim.x;

    const long n4 = (long)NN * 32;
    const float4* x4 = (const float4*)x;
    for (long j = i; j < n4; j += stride) {
        float4 v = x4[j];
        __half2 xh01 = __floats2half2_rn(v.x, v.y);
        __half2 xh23 = __floats2half2_rn(v.z, v.w);
        uint2 pk = make_uint2(*(uint32_t*)&xh01, *(uint32_t*)&xh23);
        ((uint2*)g_xh)[j] = pk;
        long node = j >> 5, c = j & 31;
        *(uint2*)((char*)g_ux + (size_t)node * 512 + c * 16 + 8) = pk;
    }
    for (long j = i; j < 256 * 128; j += stride) {
        int n = (int)(j >> 7), k = (int)(j & 127);
        int q = n >> 7, col = n & 127;
        g_Bhi[j] = __float2half_rn(W1[(size_t)(q * 128 + k) * 128 + col]);
    }
}

// ---------------------------------------------------------------------------
// CSR build (side stream): histogram -> block scan -> finalize -> scatter
// ---------------------------------------------------------------------------
__global__ void k_hist(const int* __restrict__ ei) {
    long i = (long)blockIdx.x * blockDim.x + threadIdx.x;
    long stride = (long)gridDim.x * blockDim.x;
    for (long e = i; e < NE; e += stride)
        atomicAdd(&g_cnt[ei[NE + e]], 1);
}

__global__ void k_scan1() {
    const int b = blockIdx.x, t = threadIdx.x;
    const int i = b * 256 + t;
    int v = (i < NN) ? g_cnt[i] : 0;
    const int lane = t & 31, w = t >> 5;
    #pragma unroll
    for (int o = 1; o < 32; o <<= 1) {
        int n = __shfl_up_sync(0xffffffffu, v, o);
        if (lane >= o) v += n;
    }
    __shared__ int ws[8];
    if (lane == 31) ws[w] = v;
    __syncthreads();
    if (w == 0 && lane < 8) {
        int s = ws[lane];
        #pragma unroll
        for (int o = 1; o < 8; o <<= 1) {
            int n = __shfl_up_sync(0xffu, s, o);
            if (lane >= o) s += n;
        }
        ws[lane] = s;
    }
    __syncthreads();
    if (w > 0) v += ws[w - 1];
    if (i < NN) g_off[i + 1] = v;     // block-local inclusive
    if (t == 255) g_bsum[b] = v;      // raw block total
}

__global__ void k_scan23() {
    const int b = blockIdx.x, t = threadIdx.x;
    int part = 0;
    for (int j = t; j < b; j += 256) part += g_bsum[j];
    const int lane = t & 31, w = t >> 5;
    #pragma unroll
    for (int o = 16; o; o >>= 1) part += __shfl_xor_sync(0xffffffffu, part, o);
    __shared__ int ws[8];
    if (lane == 0) ws[w] = part;
    __syncthreads();
    __shared__ int pfx;
    if (t == 0) pfx = ws[0] + ws[1] + ws[2] + ws[3] + ws[4] + ws[5] + ws[6] + ws[7];
    __syncthreads();
    const int prefix = pfx;

    const int j = b * 256 + t;
    if (j == 0) g_off[0] = 0;
    if (j < NN) {
        int incl = g_off[j + 1] + prefix;
        g_off[j + 1] = incl;
        g_ptr[j] = incl - g_cnt[j];
    }
}

__global__ void k_scat(const int* __restrict__ ei, const float* __restrict__ ew) {
    long i = (long)blockIdx.x * blockDim.x + threadIdx.x;
    long stride = (long)gridDim.x * blockDim.x;
    for (long e = i; e < NE; e += stride) {
        int tg = ei[NE + e];
        int pos = atomicAdd(&g_ptr[tg], 1);
        g_srcw[pos] = make_int2(ei[e], __float_as_int(ew[e]));
    }
}

// ---------------------------------------------------------------------------
// K1: tensor-core GEMM (mma.sync fp16, single term). R13 tile shape.
// ---------------------------------------------------------------------------
#define ROWB      272
#define AS_OFF    0
#define BH_OFF    (128 * ROWB)
#define SMEM_MMA  (2 * 128 * ROWB)

__device__ __forceinline__ void mma_fp16(float* d, const uint32_t* a, const uint32_t* b) {
    asm volatile(
        "mma.sync.aligned.m16n8k16.row.col.f32.f16.f16.f32 "
        "{%0,%1,%2,%3}, {%4,%5,%6,%7}, {%8,%9}, {%0,%1,%2,%3};"
        : "+f"(d[0]), "+f"(d[1]), "+f"(d[2]), "+f"(d[3])
        : "r"(a[0]), "r"(a[1]), "r"(a[2]), "r"(a[3]), "r"(b[0]), "r"(b[1]));
}

__device__ __forceinline__ void ldsm_x4(uint32_t* r, uint32_t addr) {
    asm volatile("ldmatrix.sync.aligned.m8n8.x4.shared.b16 {%0,%1,%2,%3}, [%4];"
                 : "=r"(r[0]), "=r"(r[1]), "=r"(r[2]), "=r"(r[3]) : "r"(addr));
}

__global__ __launch_bounds__(256, 2) void k_mma() {
    extern __shared__ char smem[];
    const uint32_t sbase = smem_u32(smem);
    const int t = threadIdx.x;
    const int q = blockIdx.y;
    const int m0 = blockIdx.x * 128;

    // B panel for this q
    #pragma unroll
    for (int r = 0; r < 8; r++) {
        int idx = t + r * 256;
        int row = idx >> 4, c = idx & 15;
        *(uint4*)(smem + BH_OFF + row * ROWB + c * 16) =
            *(const uint4*)(g_Bhi + (size_t)(q * 128 + row) * 128 + c * 8);
    }
    // A panel
    #pragma unroll
    for (int r = 0; r < 8; r++) {
        int idx = t + r * 256;
        int row = idx >> 4, c = idx & 15;
        uint4 v = make_uint4(0, 0, 0, 0);
        if (m0 + row < NN)
            v = *(const uint4*)(g_xh + (size_t)(m0 + row) * 128 + c * 8);
        *(uint4*)(smem + AS_OFF + row * ROWB + c * 16) = v;
    }
    __syncthreads();

    const int wid = t >> 5, lane = t & 31;
    const int wm = (wid >> 1) * 32;
    const int wn = (wid & 1) * 64;
    const int g  = lane >> 2, tt = lane & 3;

    const uint32_t a_off = (uint32_t)((wm + (lane & 15)) * ROWB + ((lane >> 4) << 4));
    const uint32_t b_off = (uint32_t)((wn + ((lane >> 4) << 3) + (lane & 7)) * ROWB
                                      + (((lane >> 3) & 1) << 4));

    float acc[2][8][4];
    #pragma unroll
    for (int mt = 0; mt < 2; mt++)
        #pragma unroll
        for (int nt = 0; nt < 8; nt++)
            #pragma unroll
            for (int e = 0; e < 4; e++) acc[mt][nt][e] = 0.0f;

    const uint32_t aB = sbase + AS_OFF + a_off;
    const uint32_t bB = sbase + BH_OFF + b_off;
    #pragma unroll 1
    for (int ks = 0; ks < 8; ks++) {
        const uint32_t kb = ks * 32;            // k0*2 bytes
        uint32_t a[2][4], b[4][4];
        ldsm_x4(a[0], aB + kb);
        ldsm_x4(a[1], aB + 16 * ROWB + kb);
        #pragma unroll
        for (int j = 0; j < 4; j++)
            ldsm_x4(b[j], bB + j * 16 * ROWB + kb);
        #pragma unroll
        for (int mt = 0; mt < 2; mt++)
            #pragma unroll
            for (int nt = 0; nt < 8; nt++)
                mma_fp16(acc[mt][nt], a[mt], &b[nt >> 1][(nt & 1) * 2]);
    }

    #pragma unroll
    for (int mt = 0; mt < 2; mt++) {
        const int r0 = m0 + wm + mt * 16 + g;
        #pragma unroll
        for (int nt = 0; nt < 8; nt++) {
            const int ncol = wn + nt * 8 + tt * 2;
            if (q == 0) {
                const size_t off = (size_t)(ncol >> 2) * 16 + (size_t)(ncol & 3) * 2;
                if (r0 < NN) {
                    __half2 h = __floats2half2_rn(acc[mt][nt][0], acc[mt][nt][1]);
                    *(__half2*)((char*)g_ux + (size_t)r0 * 512 + off) = h;
                }
                if (r0 + 8 < NN) {
                    __half2 h = __floats2half2_rn(acc[mt][nt][2], acc[mt][nt][3]);
                    *(__half2*)((char*)g_ux + (size_t)(r0 + 8) * 512 + off) = h;
                }
            } else {
                if (r0 < NN)
                    *(float2*)(g_v + (size_t)r0 * 128 + ncol) =
                        make_float2(acc[mt][nt][0], acc[mt][nt][1]);
                if (r0 + 8 < NN)
                    *(float2*)(g_v + (size_t)(r0 + 8) * 128 + ncol) =
                        make_float2(acc[mt][nt][2], acc[mt][nt][3]);
            }
        }
    }
}

// ---------------------------------------------------------------------------
// K2: persistent warp-strided node loop; proven 2-edge inner body; __expf.
//     Re-zeros g_cnt for the next call.
// ---------------------------------------------------------------------------
__global__ __launch_bounds__(256) void k_edge2(
    const float* __restrict__ x,
    const float* __restrict__ W1, const float* __restrict__ b1,
    const float* __restrict__ W2, const float* __restrict__ b2,
    float* __restrict__ out)
{
    __shared__ float sW1c[HID], sb1[HID], sW2[HID];
    __shared__ float sb2;
    const int t = threadIdx.x;
    if (t < HID) {
        sW1c[t] = W1[256 * HID + t];
        sb1[t]  = b1[t];
        sW2[t]  = W2[t];
    }
    if (t == 0) sb2 = b2[0];

    // zero g_cnt for the next call (grid-stride; EBLK*256 = 151552 >= NN)
    for (int gi = blockIdx.x * 256 + t; gi < NN; gi += EBLK * 256)
        g_cnt[gi] = 0;
    __syncthreads();

    const int warp = t >> 5, lane = t & 31;
    const int gw = blockIdx.x * 8 + warp;

    const float4 wc = *(const float4*)&sW1c[lane * 4];
    const float4 bb = *(const float4*)&sb1[lane * 4];
    const float4 w2 = *(const float4*)&sW2[lane * 4];
    const float  lb2 = sb2;

    for (int node = gw; node < NN; node += NWARP) {
        const int beg = g_off[node], end = g_off[node + 1];

        const float4 v  = ((const float4*)(g_v + (size_t)node * 128))[lane];
        const float4 xt = ((const float4*)(x + (size_t)node * HID))[lane];

        float sum = 0.0f;
        float4 num = make_float4(0.f, 0.f, 0.f, 0.f);

        int i = beg;
        for (; i + 2 <= end; i += 2) {
            const int2 sw0 = g_srcw[i];
            const int2 sw1 = g_srcw[i + 1];
            const float w0 = __int_as_float(sw0.y);
            const float w1 = __int_as_float(sw1.y);
            const uint4 r0 = *(const uint4*)((const char*)g_ux + (size_t)sw0.x * 512 + lane * 16);
            const uint4 r1 = *(const uint4*)((const char*)g_ux + (size_t)sw1.x * 512 + lane * 16);

            float2 u0a = __half22float2(*(const __half2*)&r0.x);
            float2 u0b = __half22float2(*(const __half2*)&r0.y);
            float2 x0a = __half22float2(*(const __half2*)&r0.z);
            float2 x0b = __half22float2(*(const __half2*)&r0.w);
            float2 u1a = __half22float2(*(const __half2*)&r1.x);
            float2 u1b = __half22float2(*(const __half2*)&r1.y);
            float2 x1a = __half22float2(*(const __half2*)&r1.z);
            float2 x1b = __half22float2(*(const __half2*)&r1.w);

            float a0 = fmaxf(fmaf(w0, wc.x, u0a.x + v.x) + bb.x, 0.f);
            float a1 = fmaxf(fmaf(w0, wc.y, u0a.y + v.y) + bb.y, 0.f);
            float a2 = fmaxf(fmaf(w0, wc.z, u0b.x + v.z) + bb.z, 0.f);
            float a3 = fmaxf(fmaf(w0, wc.w, u0b.y + v.w) + bb.w, 0.f);
            float p0 = a0 * w2.x + a1 * w2.y + a2 * w2.z + a3 * w2.w;

            float c0 = fmaxf(fmaf(w1, wc.x, u1a.x + v.x) + bb.x, 0.f);
            float c1 = fmaxf(fmaf(w1, wc.y, u1a.y + v.y) + bb.y, 0.f);
            float c2 = fmaxf(fmaf(w1, wc.z, u1b.x + v.z) + bb.z, 0.f);
            float c3 = fmaxf(fmaf(w1, wc.w, u1b.y + v.w) + bb.w, 0.f);
            float p1 = c0 * w2.x + c1 * w2.y + c2 * w2.z + c3 * w2.w;

            #pragma unroll
            for (int o = 16; o; o >>= 1) {
                p0 += __shfl_xor_sync(0xffffffffu, p0, o);
                p1 += __shfl_xor_sync(0xffffffffu, p1, o);
            }
            const float e0 = __expf(p0 + lb2);
            const float e1 = __expf(p1 + lb2);
            sum += e0 + e1;
            num.x += e0 * x0a.x + e1 * x1a.x;
            num.y += e0 * x0a.y + e1 * x1a.y;
            num.z += e0 * x0b.x + e1 * x1b.x;
            num.w += e0 * x0b.y + e1 * x1b.y;
        }
        if (i < end) {
            const int2 sw0 = g_srcw[i];
            const float w0 = __int_as_float(sw0.y);
            const uint4 r0 = *(const uint4*)((const char*)g_ux + (size_t)sw0.x * 512 + lane * 16);
            float2 u0a = __half22float2(*(const __half2*)&r0.x);
            float2 u0b = __half22float2(*(const __half2*)&r0.y);
            float2 x0a = __half22float2(*(const __half2*)&r0.z);
            float2 x0b = __half22float2(*(const __half2*)&r0.w);
            float a0 = fmaxf(fmaf(w0, wc.x, u0a.x + v.x) + bb.x, 0.f);
            float a1 = fmaxf(fmaf(w0, wc.y, u0a.y + v.y) + bb.y, 0.f);
            float a2 = fmaxf(fmaf(w0, wc.z, u0b.x + v.z) + bb.z, 0.f);
            float a3 = fmaxf(fmaf(w0, wc.w, u0b.y + v.w) + bb.w, 0.f);
            float p0 = a0 * w2.x + a1 * w2.y + a2 * w2.z + a3 * w2.w;
            #pragma unroll
            for (int o = 16; o; o >>= 1) p0 += __shfl_xor_sync(0xffffffffu, p0, o);
            const float e0 = __expf(p0 + lb2);
            sum += e0;
            num.x += e0 * x0a.x; num.y += e0 * x0a.y;
            num.z += e0 * x0b.x; num.w += e0 * x0b.y;
        }

        const float inv = 1.0f / fmaxf(sum, 1e-12f);
        float4 o4 = make_float4(fmaf(num.x, inv, xt.x), fmaf(num.y, inv, xt.y),
                                fmaf(num.z, inv, xt.z), fmaf(num.w, inv, xt.w));
        ((float4*)(out + (size_t)node * HID))[lane] = o4;
    }
}

// ---------------------------------------------------------------------------
// Fork-join pipeline:
//   main stream  : cvtx ───────────► mma ─────────┐
//   side stream  : hist ► scan1 ► scan23 ► scat ──┴► edge2 (main)
// Events/streamWaitEvent are graph-capturable (become graph edges).
// ---------------------------------------------------------------------------
extern "C" void kernel_launch(void* const* d_in, const int* in_sizes, int n_in,
                              void* d_out, int out_size)
{
    const float* x  = (const float*)d_in[0];
    const int*   ei = (const int*)d_in[1];
    const float* ew = (const float*)d_in[2];
    const float* W1 = (const float*)d_in[3];
    const float* b1 = (const float*)d_in[4];
    const float* W2 = (const float*)d_in[5];
    const float* b2 = (const float*)d_in[6];
    float* out = (float*)d_out;

    static cudaStream_t sB = nullptr;
    static cudaEvent_t  eFork = nullptr, eJoin = nullptr;
    if (!sB) {
        cudaStreamCreateWithFlags(&sB, cudaStreamNonBlocking);
        cudaEventCreateWithFlags(&eFork, cudaEventDisableTiming);
        cudaEventCreateWithFlags(&eJoin, cudaEventDisableTiming);
        cudaFuncSetAttribute(k_mma, cudaFuncAttributeMaxDynamicSharedMemorySize, SMEM_MMA);
    }

    // fork: side stream inherits capture via event wait
    cudaEventRecord(eFork, 0);
    cudaStreamWaitEvent(sB, eFork, 0);

    // side stream: CSR build (independent of x/W conversion)
    k_hist<<<1024, 256, 0, sB>>>(ei);
    k_scan1<<<NSB, 256, 0, sB>>>();
    k_scan23<<<NSB, 256, 0, sB>>>();
    k_scat<<<1024, 256, 0, sB>>>(ei, ew);
    cudaEventRecord(eJoin, sB);

    // main stream: conversions + GEMM
    k_cvtx<<<2048, 256>>>(x, W1);
    dim3 gg((NN + 127) / 128, 2);
    k_mma<<<gg, 256, SMEM_MMA>>>();

    // join, then the fused edge pass
    cudaStreamWaitEvent(0, eJoin, 0);
    k_edge2<<<EBLK, 256>>>(x, W1, b1, W2, b2, out);
}